// round 10
// baseline (speedup 1.0000x reference)
#include <cuda_runtime.h>
#include <cuda_fp16.h>
#include <math.h>
#include <stdint.h>

// Problem constants
#define NB   4
#define LL   2048
#define CC   1024
#define KK   7
#define MM   (NB * LL)   // 8192

// Scratch (allocation-free rule: __device__ globals)
__device__ __half g_wih[CC * CC];    // fp16 Wi
__device__ __half g_woh[CC * CC];    // fp16 Wout
__device__ __half g_woh7[KK * CC];   // fp16 Wo (offset head)
__device__ __half g_wmh7[KK * CC];   // fp16 Wm (mask head)
__device__ __half g_xph[MM * CC];    // x_proj (fp16)
__device__ __half g_xdw[MM * CC];    // conv+LN+GELU result (fp16)
__device__ __half g_samph[MM * CC];  // sampled (fp16)
__device__ float  g_recw[MM * 16];   // per-position blend weights (wf[8], wc[8])
__device__ int    g_reci[MM * 16];   // per-position gather indices (pf[8], pc[8])

// ---------------------------------------------------------------------------
// helpers
// ---------------------------------------------------------------------------
__device__ __forceinline__ uint32_t smem_u32(const void* p) {
    uint32_t a;
    asm("{ .reg .u64 t; cvta.to.shared.u64 t, %1; cvt.u32.u64 %0, t; }"
        : "=r"(a) : "l"(p));
    return a;
}

__device__ __forceinline__ void mma_f16(float* d, const uint32_t* a,
                                        const uint32_t* b) {
    asm volatile(
        "mma.sync.aligned.m16n8k16.row.col.f32.f16.f16.f32 "
        "{%0,%1,%2,%3}, {%4,%5,%6,%7}, {%8,%9}, {%0,%1,%2,%3};"
        : "+f"(d[0]), "+f"(d[1]), "+f"(d[2]), "+f"(d[3])
        : "r"(a[0]), "r"(a[1]), "r"(a[2]), "r"(a[3]),
          "r"(b[0]), "r"(b[1]));
}

#define LDSM4(r0, r1, r2, r3, addr)                                           \
    asm volatile("ldmatrix.sync.aligned.m8n8.x4.shared.b16 {%0,%1,%2,%3}, [%4];" \
                 : "=r"(r0), "=r"(r1), "=r"(r2), "=r"(r3) : "r"(addr))

#define CP_ASYNC16(dst, src) \
    asm volatile("cp.async.cg.shared.global [%0], [%1], 16;" :: "r"(dst), "l"(src))
#define CP_COMMIT() asm volatile("cp.async.commit_group;" ::: "memory")
#define CP_WAIT1()  asm volatile("cp.async.wait_group 1;" ::: "memory")

__device__ __forceinline__ void store_out(float2 v, float* p) {
    *(float2*)p = v;
}
__device__ __forceinline__ void store_out(float2 v, __half* p) {
    *(__half2*)p = __floats2half2_rn(v.x, v.y);
}

// ---------------------------------------------------------------------------
// fp32 -> fp16 conversion pre-pass (weights only)
// ---------------------------------------------------------------------------
__global__ __launch_bounds__(256)
void cvt_f16(const float4* __restrict__ in, uint2* __restrict__ out, int n4) {
    int i = blockIdx.x * blockDim.x + threadIdx.x;
    if (i < n4) {
        float4 v = in[i];
        __half2 h0 = __floats2half2_rn(v.x, v.y);
        __half2 h1 = __floats2half2_rn(v.z, v.w);
        uint2 o;
        o.x = *(uint32_t*)&h0;
        o.y = *(uint32_t*)&h1;
        out[i] = o;
    }
}

// ---------------------------------------------------------------------------
// GEMM common pieces: 128x128 CTA tile, BK=64, 8 warps (4x2), 32x64 warp
// tile, 256 threads, XOR swizzle, ldmatrix fragments, templated output.
// ---------------------------------------------------------------------------
#define TILE_BYTES 16384

// B operand staging via cp.async (fp16 source)
__device__ __forceinline__ void stage_b(uint32_t bbase,
                                        const __half* __restrict__ B,
                                        int bn, int k0, int tid) {
#pragma unroll
    for (int i = 0; i < 4; ++i) {
        int f = i * 256 + tid;
        int row = f >> 3, c4 = f & 7;
        uint32_t dst = bbase + row * 128 + ((c4 ^ (row & 7)) << 4);
        const __half* src = B + (size_t)(bn + row) * 1024 + k0 + c4 * 8;
        CP_ASYNC16(dst, src);
    }
}

// A operand staging via cp.async (fp16 source)
__device__ __forceinline__ void stage_a_f16(uint32_t abase,
                                            const __half* __restrict__ A,
                                            int bm, int k0, int tid) {
#pragma unroll
    for (int i = 0; i < 4; ++i) {
        int f = i * 256 + tid;
        int row = f >> 3, c4 = f & 7;
        uint32_t dst = abase + row * 128 + ((c4 ^ (row & 7)) << 4);
        const __half* src = A + (size_t)(bm + row) * 1024 + k0 + c4 * 8;
        CP_ASYNC16(dst, src);
    }
}

// A operand staging from fp32 source: LDG.128 x2 -> cvt -> STS.128
__device__ __forceinline__ void stage_a_f32(uint32_t abase,
                                            const float* __restrict__ A,
                                            int bm, int k0, int tid) {
#pragma unroll
    for (int i = 0; i < 4; ++i) {
        int f = i * 256 + tid;
        int row = f >> 3, c8 = f & 7;
        const float* src = A + (size_t)(bm + row) * 1024 + k0 + c8 * 8;
        float4 v0 = *(const float4*)(src);
        float4 v1 = *(const float4*)(src + 4);
        __half2 h0 = __floats2half2_rn(v0.x, v0.y);
        __half2 h1 = __floats2half2_rn(v0.z, v0.w);
        __half2 h2 = __floats2half2_rn(v1.x, v1.y);
        __half2 h3 = __floats2half2_rn(v1.z, v1.w);
        uint32_t dst = abase + row * 128 + ((c8 ^ (row & 7)) << 4);
        asm volatile("st.shared.v4.b32 [%0], {%1,%2,%3,%4};"
                     :: "r"(dst),
                        "r"(*(uint32_t*)&h0), "r"(*(uint32_t*)&h1),
                        "r"(*(uint32_t*)&h2), "r"(*(uint32_t*)&h3) : "memory");
    }
}

// Fragment addresses + compute for one BK=64 stage
struct FragCtx {
    uint32_t aRowOff[2], aSw[2];
    uint32_t bRowOff[4], bSw[4];
    int aHi, bHi;
};

__device__ __forceinline__ void frag_init(FragCtx& fc, int lane, int wm, int wn) {
    fc.aHi = (lane >> 4) & 1;
#pragma unroll
    for (int i = 0; i < 2; ++i) {
        int rowA = wm * 32 + i * 16 + (lane & 15);
        fc.aRowOff[i] = (uint32_t)(rowA * 128);
        fc.aSw[i] = (uint32_t)(rowA & 7);
    }
    fc.bHi = (lane >> 3) & 1;
#pragma unroll
    for (int j2 = 0; j2 < 4; ++j2) {
        int rowB = wn * 64 + j2 * 16 + ((lane & 16) >> 1) + (lane & 7);
        fc.bRowOff[j2] = (uint32_t)(rowB * 128);
        fc.bSw[j2] = (uint32_t)(rowB & 7);
    }
}

__device__ __forceinline__ void compute_stage(const FragCtx& fc, uint32_t aBase,
                                              uint32_t bBase, float d[2][8][4]) {
#pragma unroll
    for (int ks = 0; ks < 4; ++ks) {
        const uint32_t granA = (uint32_t)(2 * ks + fc.aHi);
        const uint32_t granB = (uint32_t)(2 * ks + fc.bHi);
        uint32_t af[2][4];
#pragma unroll
        for (int i = 0; i < 2; ++i) {
            uint32_t addr = aBase + fc.aRowOff[i] + ((granA ^ fc.aSw[i]) << 4);
            LDSM4(af[i][0], af[i][1], af[i][2], af[i][3], addr);
        }
        uint32_t bf[8][2];
#pragma unroll
        for (int j2 = 0; j2 < 4; ++j2) {
            uint32_t addr = bBase + fc.bRowOff[j2] + ((granB ^ fc.bSw[j2]) << 4);
            LDSM4(bf[2 * j2][0], bf[2 * j2][1],
                  bf[2 * j2 + 1][0], bf[2 * j2 + 1][1], addr);
        }
#pragma unroll
        for (int i = 0; i < 2; ++i)
#pragma unroll
            for (int j = 0; j < 8; ++j)
                mma_f16(d[i][j], af[i], bf[j]);
    }
}

template <typename OT>
__device__ __forceinline__ void epilogue(float d[2][8][4], const float* bias,
                                         OT* Cout, int bm, int bn,
                                         int wm, int wn, int g, int tig) {
#pragma unroll
    for (int i = 0; i < 2; ++i) {
        int row = bm + wm * 32 + i * 16 + g;
        OT* o0 = Cout + (size_t)row * 1024 + bn + wn * 64;
        OT* o1 = o0 + 8 * 1024;
#pragma unroll
        for (int j = 0; j < 8; ++j) {
            int col = j * 8 + tig * 2;
            float2 bb = *(const float2*)&bias[bn + wn * 64 + col];
            float2 v0, v1;
            v0.x = d[i][j][0] + bb.x;
            v0.y = d[i][j][1] + bb.y;
            v1.x = d[i][j][2] + bb.x;
            v1.y = d[i][j][3] + bb.y;
            store_out(v0, o0 + col);
            store_out(v1, o1 + col);
        }
    }
}

// ---- GEMM variant 1: A fp32 in gmem (converted in staging), B fp16 ----
// SMEM: A bufs 2 x 16KB at 0; B bufs 3 x 16KB at 32768. Total 80KB.
#define SMEM_F32A (2 * TILE_BYTES + 3 * TILE_BYTES)

__global__ __launch_bounds__(256, 2)
void mma_gemm_f32a(const float* __restrict__ A, const __half* __restrict__ B,
                   const float* __restrict__ bias, __half* __restrict__ Cout) {
    extern __shared__ char dyn_smem[];
    const uint32_t sb = smem_u32(dyn_smem);
    const uint32_t sbB = sb + 2 * TILE_BYTES;

    const int tid  = threadIdx.x;
    const int wid  = tid >> 5;
    const int lane = tid & 31;
    const int g    = lane >> 2;
    const int tig  = lane & 3;
    const int wm   = wid >> 1;
    const int wn   = wid & 1;
    const int bm = blockIdx.y * 128;
    const int bn = blockIdx.x * 128;

    float d[2][8][4];
#pragma unroll
    for (int i = 0; i < 2; ++i)
#pragma unroll
        for (int j = 0; j < 8; ++j)
#pragma unroll
            for (int r = 0; r < 4; ++r) d[i][j][r] = 0.f;

    FragCtx fc;
    frag_init(fc, lane, wm, wn);

    // prologue: B stages 0,1 via cp.async
    stage_b(sbB + 0 * TILE_BYTES, B, bn, 0, tid);
    CP_COMMIT();
    stage_b(sbB + 1 * TILE_BYTES, B, bn, 64, tid);
    CP_COMMIT();

#pragma unroll 1
    for (int s = 0; s < 16; ++s) {
        // synchronous fp32->fp16 A staging (hides behind the cp.async wait)
        stage_a_f32(sb + (s & 1) * TILE_BYTES, A, bm, s * 64, tid);

        CP_WAIT1();        // B_s complete
        __syncthreads();   // A_s STS + B_s visible; prior compute drained

        if (s + 2 < 16)
            stage_b(sbB + ((s + 2) % 3) * TILE_BYTES, B, bn, (s + 2) * 64, tid);
        CP_COMMIT();

        compute_stage(fc, sb + (s & 1) * TILE_BYTES,
                      sbB + (s % 3) * TILE_BYTES, d);
    }

    epilogue(d, bias, Cout, bm, bn, wm, wn, g, tig);
}

// ---- GEMM variant 2: both operands fp16 (3-stage cp.async) ----
#define SMEM_F16 (3 * 2 * TILE_BYTES)

template <typename OT>
__global__ __launch_bounds__(256, 2)
void mma_gemm(const __half* __restrict__ A, const __half* __restrict__ B,
              const float* __restrict__ bias, OT* __restrict__ Cout) {
    extern __shared__ char dyn_smem[];
    const uint32_t sb = smem_u32(dyn_smem);

    const int tid  = threadIdx.x;
    const int wid  = tid >> 5;
    const int lane = tid & 31;
    const int g    = lane >> 2;
    const int tig  = lane & 3;
    const int wm   = wid >> 1;
    const int wn   = wid & 1;
    const int bm = blockIdx.y * 128;
    const int bn = blockIdx.x * 128;

    float d[2][8][4];
#pragma unroll
    for (int i = 0; i < 2; ++i)
#pragma unroll
        for (int j = 0; j < 8; ++j)
#pragma unroll
            for (int r = 0; r < 4; ++r) d[i][j][r] = 0.f;

    FragCtx fc;
    frag_init(fc, lane, wm, wn);

    stage_a_f16(sb + 0 * 32768, A, bm, 0, tid);
    stage_b(sb + 0 * 32768 + TILE_BYTES, B, bn, 0, tid);
    CP_COMMIT();
    stage_a_f16(sb + 1 * 32768, A, bm, 64, tid);
    stage_b(sb + 1 * 32768 + TILE_BYTES, B, bn, 64, tid);
    CP_COMMIT();

#pragma unroll 1
    for (int s = 0; s < 16; ++s) {
        CP_WAIT1();
        __syncthreads();

        if (s + 2 < 16) {
            stage_a_f16(sb + ((s + 2) % 3) * 32768, A, bm, (s + 2) * 64, tid);
            stage_b(sb + ((s + 2) % 3) * 32768 + TILE_BYTES, B, bn,
                    (s + 2) * 64, tid);
        }
        CP_COMMIT();

        const uint32_t base = sb + (s % 3) * 32768;
        compute_stage(fc, base, base + TILE_BYTES, d);
    }

    epilogue(d, bias, Cout, bm, bn, wm, wn, g, tig);
}

// ---------------------------------------------------------------------------
// Kernel A: depthwise conv(k=3,pad=1) + LayerNorm + exact GELU -> x_dw fp16.
// One block (256 thr) per (n,l); 4 channels per thread.
// ---------------------------------------------------------------------------
__global__ __launch_bounds__(256)
void conv_ln_gelu(const float* __restrict__ x,
                  const float* __restrict__ dw_w, const float* __restrict__ dw_b,
                  const float* __restrict__ ln_g, const float* __restrict__ ln_b,
                  __half* __restrict__ xdw) {
    const int nl = blockIdx.x;           // 0..8191
    const int l = nl & (LL - 1);
    const int tid = threadIdx.x;
    const int lane = tid & 31;
    const int wid = tid >> 5;
    const int c0 = tid * 4;

    const float* x0 = x + (size_t)nl * CC;

    float4 xm = *(const float4*)(x0 + c0);
    float4 xl = (l > 0)      ? *(const float4*)(x0 + c0 - CC) : make_float4(0,0,0,0);
    float4 xr = (l < LL - 1) ? *(const float4*)(x0 + c0 + CC) : make_float4(0,0,0,0);
    float4 db = *(const float4*)(dw_b + c0);
    float v[4];
    {
        const float* wp = dw_w + c0 * 3;
        v[0] = db.x + xl.x * wp[0]  + xm.x * wp[1]  + xr.x * wp[2];
        v[1] = db.y + xl.y * wp[3]  + xm.y * wp[4]  + xr.y * wp[5];
        v[2] = db.z + xl.z * wp[6]  + xm.z * wp[7]  + xr.z * wp[8];
        v[3] = db.w + xl.w * wp[9]  + xm.w * wp[10] + xr.w * wp[11];
    }

    float s  = v[0] + v[1] + v[2] + v[3];
    float s2 = v[0]*v[0] + v[1]*v[1] + v[2]*v[2] + v[3]*v[3];
#pragma unroll
    for (int o = 16; o; o >>= 1) {
        s  += __shfl_xor_sync(0xFFFFFFFFu, s,  o);
        s2 += __shfl_xor_sync(0xFFFFFFFFu, s2, o);
    }
    __shared__ float rs[8], rs2[8];
    __shared__ float stats[2];
    if (lane == 0) { rs[wid] = s; rs2[wid] = s2; }
    __syncthreads();
    if (tid == 0) {
        float S = 0.f, S2 = 0.f;
#pragma unroll
        for (int w = 0; w < 8; ++w) { S += rs[w]; S2 += rs2[w]; }
        float mu = S * (1.f / CC);
        float var = S2 * (1.f / CC) - mu * mu;
        stats[0] = mu;
        stats[1] = rsqrtf(var + 1e-5f);
    }
    __syncthreads();
    const float mu = stats[0], rstd = stats[1];

    float4 lg = *(const float4*)(ln_g + c0);
    float4 lb = *(const float4*)(ln_b + c0);
    float g0, g1, g2, g3, h;
    h = (v[0] - mu) * rstd * lg.x + lb.x;
    g0 = 0.5f * h * (1.f + erff(h * 0.70710678118654752f));
    h = (v[1] - mu) * rstd * lg.y + lb.y;
    g1 = 0.5f * h * (1.f + erff(h * 0.70710678118654752f));
    h = (v[2] - mu) * rstd * lg.z + lb.z;
    g2 = 0.5f * h * (1.f + erff(h * 0.70710678118654752f));
    h = (v[3] - mu) * rstd * lg.w + lb.w;
    g3 = 0.5f * h * (1.f + erff(h * 0.70710678118654752f));

    __half2 h0 = __floats2half2_rn(g0, g1);
    __half2 h1 = __floats2half2_rn(g2, g3);
    uint2 ov;
    ov.x = *(uint32_t*)&h0;
    ov.y = *(uint32_t*)&h1;
    *(uint2*)(xdw + (size_t)nl * CC + c0) = ov;
}

// ---------------------------------------------------------------------------
// Kernel B: offset/mask heads (fp16 weights) + softmax + positions.
// Warp per position, 8 positions per block, no __syncthreads.
// ---------------------------------------------------------------------------
__global__ __launch_bounds__(256)
void heads_pos(const __half* __restrict__ xdw,
               const __half* __restrict__ Woh, const float* __restrict__ bo,
               const __half* __restrict__ Wmh, const float* __restrict__ bmv,
               float* __restrict__ recw, int* __restrict__ reci) {
    const int wid  = threadIdx.x >> 5;
    const int lane = threadIdx.x & 31;
    const int pos  = blockIdx.x * 8 + wid;
    const int l    = pos & (LL - 1);

    const __half2* xr  = (const __half2*)(xdw + (size_t)pos * CC);
    const __half2* wo2 = (const __half2*)Woh;
    const __half2* wm2 = (const __half2*)Wmh;

    float p[14];
#pragma unroll
    for (int j = 0; j < 14; ++j) p[j] = 0.f;

#pragma unroll
    for (int i = 0; i < 16; ++i) {
        int c2 = lane + 32 * i;          // half2 index, 0..511
        float2 f = __half22float2(xr[c2]);
#pragma unroll
        for (int j = 0; j < 7; ++j) {
            float2 w1 = __half22float2(wo2[j * 512 + c2]);
            float2 w2 = __half22float2(wm2[j * 512 + c2]);
            p[j]     = fmaf(f.x, w1.x, fmaf(f.y, w1.y, p[j]));
            p[7 + j] = fmaf(f.x, w2.x, fmaf(f.y, w2.y, p[7 + j]));
        }
    }
#pragma unroll
    for (int o = 16; o; o >>= 1)
#pragma unroll
        for (int j = 0; j < 14; ++j)
            p[j] += __shfl_xor_sync(0xFFFFFFFFu, p[j], o);

    if (lane == 0) {
        float ho[KK], hm[KK];
#pragma unroll
        for (int j = 0; j < KK; ++j) {
            ho[j] = (p[j] + bo[j]) * 2.0f;     // OFFSET_SCALE
            hm[j] = p[7 + j] + bmv[j];
        }
        float mx = hm[0];
#pragma unroll
        for (int j = 1; j < KK; ++j) mx = fmaxf(mx, hm[j]);
        float e[KK], se = 0.f;
#pragma unroll
        for (int j = 0; j < KK; ++j) { e[j] = expf(hm[j] - mx); se += e[j]; }
        float inv = 1.f / se;

        float* rw = recw + (size_t)pos * 16;
        int*   ri = reci + (size_t)pos * 16;
#pragma unroll
        for (int k = 0; k < KK; ++k) {
            float mask = e[k] * inv;
            float ap  = (float)l + (float)(k - 3) + ho[k];
            float apc = fminf(fmaxf(ap, 0.f), (float)(LL - 1));
            int pf = (int)apc;
            if (pf > LL - 1) pf = LL - 1;
            int pc = pf + 1; if (pc > LL - 1) pc = LL - 1;
            float wc = apc - (float)pf;
            float wf = 1.f - wc;
            float valid = (ap < 0.f || ap > (float)(LL - 1)) ? 0.f : 1.f;
            rw[k]     = wf * valid * mask;
            rw[8 + k] = wc * valid * mask;
            ri[k]     = pf;
            ri[8 + k] = pc;
        }
    }
}

// ---------------------------------------------------------------------------
// Kernel C: gather-blend from fp16 x_proj -> sampled fp16.
// One block (128 thr) per position, 8 channels per thread, no __syncthreads.
// ---------------------------------------------------------------------------
__global__ __launch_bounds__(128)
void gather_blend(const __half* __restrict__ xph,
                  const float* __restrict__ recw, const int* __restrict__ reci,
                  __half* __restrict__ samp) {
    const int nl = blockIdx.x;
    const int n  = nl >> 11;
    const int c0 = threadIdx.x * 8;

    const float* rw = recw + (size_t)nl * 16;
    const int*   ri = reci + (size_t)nl * 16;

    float wf[KK], wc[KK];
    int   pf[KK], pc[KK];
#pragma unroll
    for (int k = 0; k < KK; ++k) {
        wf[k] = __ldg(rw + k);
        wc[k] = __ldg(rw + 8 + k);
        pf[k] = __ldg(ri + k);
        pc[k] = __ldg(ri + 8 + k);
    }

    const __half* xpn = xph + (size_t)n * LL * CC + c0;

    float acc[8];
#pragma unroll
    for (int m = 0; m < 8; ++m) acc[m] = 0.f;

#pragma unroll
    for (int k = 0; k < KK; ++k) {
        uint4 rf = *(const uint4*)(xpn + (size_t)pf[k] * CC);
        uint4 rc = *(const uint4*)(xpn + (size_t)pc[k] * CC);
        float w0 = wf[k], w1 = wc[k];
        const __half2* hf = (const __half2*)&rf;
        const __half2* hc = (const __half2*)&rc;
#pragma unroll
        for (int m = 0; m < 4; ++m) {
            float2 ff = __half22float2(hf[m]);
            float2 fc = __half22float2(hc[m]);
            acc[2*m + 0] = fmaf(ff.x, w0, fmaf(fc.x, w1, acc[2*m + 0]));
            acc[2*m + 1] = fmaf(ff.y, w0, fmaf(fc.y, w1, acc[2*m + 1]));
        }
    }

    uint4 ov;
    __half2 o0 = __floats2half2_rn(acc[0], acc[1]);
    __half2 o1 = __floats2half2_rn(acc[2], acc[3]);
    __half2 o2 = __floats2half2_rn(acc[4], acc[5]);
    __half2 o3 = __floats2half2_rn(acc[6], acc[7]);
    ov.x = *(uint32_t*)&o0; ov.y = *(uint32_t*)&o1;
    ov.z = *(uint32_t*)&o2; ov.w = *(uint32_t*)&o3;
    *(uint4*)(samp + (size_t)nl * CC + c0) = ov;
}

// ---------------------------------------------------------------------------
// Launch — GEMM1 is now independent of A (reads x fp32 directly):
//
//   main: cvt_wi -> GEMM1'(x,wih->xph) -[wait evB]-> C -> GEMM2
//   side: cvt_wo, cvt_wo7, cvt_wm7 -> A(x->xdw) -> B -> [evB]
// ---------------------------------------------------------------------------
extern "C" void kernel_launch(void* const* d_in, const int* in_sizes, int n_in,
                              void* d_out, int out_size) {
    const float* x    = (const float*)d_in[0];
    const float* Wi   = (const float*)d_in[1];
    const float* bi   = (const float*)d_in[2];
    const float* dw_w = (const float*)d_in[3];
    const float* dw_b = (const float*)d_in[4];
    const float* ln_g = (const float*)d_in[5];
    const float* ln_b = (const float*)d_in[6];
    const float* Wo   = (const float*)d_in[7];
    const float* bo   = (const float*)d_in[8];
    const float* Wm   = (const float*)d_in[9];
    const float* bmv  = (const float*)d_in[10];
    const float* Wout = (const float*)d_in[11];
    const float* bout = (const float*)d_in[12];
    float* out = (float*)d_out;

    __half *wih, *woh, *woh7, *wmh7, *xph, *xdw, *samph;
    float *recw;
    int *reci;
    cudaGetSymbolAddress((void**)&wih,   g_wih);
    cudaGetSymbolAddress((void**)&woh,   g_woh);
    cudaGetSymbolAddress((void**)&woh7,  g_woh7);
    cudaGetSymbolAddress((void**)&wmh7,  g_wmh7);
    cudaGetSymbolAddress((void**)&xph,   g_xph);
    cudaGetSymbolAddress((void**)&xdw,   g_xdw);
    cudaGetSymbolAddress((void**)&samph, g_samph);
    cudaGetSymbolAddress((void**)&recw,  g_recw);
    cudaGetSymbolAddress((void**)&reci,  g_reci);

    cudaFuncSetAttribute(mma_gemm_f32a,
                         cudaFuncAttributeMaxDynamicSharedMemorySize, SMEM_F32A);
    cudaFuncSetAttribute(mma_gemm<float>,
                         cudaFuncAttributeMaxDynamicSharedMemorySize, SMEM_F16);

    // One-time host-side stream/event creation (no device memory involved).
    static cudaStream_t s_side = nullptr;
    static cudaEvent_t  ev_fork = nullptr, ev_b = nullptr;
    if (s_side == nullptr) {
        cudaStreamCreateWithFlags(&s_side, cudaStreamNonBlocking);
        cudaEventCreateWithFlags(&ev_fork, cudaEventDisableTiming);
        cudaEventCreateWithFlags(&ev_b,    cudaEventDisableTiming);
    }

    dim3 gemm_grid(CC / 128, MM / 128);   // (8, 64)

    // Fork side stream off the main (legacy) stream.
    cudaEventRecord(ev_fork, 0);
    cudaStreamWaitEvent(s_side, ev_fork, 0);

    // side: weight conversions, then A, then B
    cvt_f16<<<(CC * CC / 4) / 256, 256, 0, s_side>>>(
        (const float4*)Wout, (uint2*)woh, CC * CC / 4);
    cvt_f16<<<(KK * CC / 4 + 255) / 256, 256, 0, s_side>>>(
        (const float4*)Wo, (uint2*)woh7, KK * CC / 4);
    cvt_f16<<<(KK * CC / 4 + 255) / 256, 256, 0, s_side>>>(
        (const float4*)Wm, (uint2*)wmh7, KK * CC / 4);
    conv_ln_gelu<<<MM, 256, 0, s_side>>>(x, dw_w, dw_b, ln_g, ln_b, xdw);
    heads_pos<<<MM / 8, 256, 0, s_side>>>(xdw, woh7, bo, wmh7, bmv, recw, reci);
    cudaEventRecord(ev_b, s_side);

    // main: cvt Wi, GEMM1' (reads x fp32 directly — no dependency on A)
    cvt_f16<<<(CC * CC / 4) / 256, 256>>>((const float4*)Wi, (uint2*)wih,
                                          CC * CC / 4);
    mma_gemm_f32a<<<gemm_grid, 256, SMEM_F32A>>>(x, wih, bi, xph);

    // join, then C and GEMM2
    cudaStreamWaitEvent(0, ev_b, 0);
    gather_blend<<<MM, 128>>>(xph, recw, reci, samph);
    mma_gemm<float><<<gemm_grid, 256, SMEM_F16>>>(samph, woh, bout, out);
}

// round 11
// speedup vs baseline: 1.0220x; 1.0220x over previous
#include <cuda_runtime.h>
#include <cuda_fp16.h>
#include <math.h>
#include <stdint.h>

// Problem constants
#define NB   4
#define LL   2048
#define CC   1024
#define KK   7
#define MM   (NB * LL)   // 8192
#define HM   (MM / 2)    // 4096 rows per chunk (= 2 batches)

// Scratch (allocation-free rule: __device__ globals)
__device__ __half g_xh[MM * CC];     // fp16 x
__device__ __half g_wih[CC * CC];    // fp16 Wi
__device__ __half g_woh[CC * CC];    // fp16 Wout
__device__ __half g_woh7[KK * CC];   // fp16 Wo (offset head)
__device__ __half g_wmh7[KK * CC];   // fp16 Wm (mask head)
__device__ __half g_xph[MM * CC];    // x_proj (fp16)
__device__ __half g_xdw[MM * CC];    // conv+LN+GELU result (fp16)
__device__ __half g_samph[MM * CC];  // sampled (fp16)
__device__ float  g_recw[MM * 16];   // per-position blend weights
__device__ int    g_reci[MM * 16];   // per-position gather indices

// ---------------------------------------------------------------------------
// helpers
// ---------------------------------------------------------------------------
__device__ __forceinline__ uint32_t smem_u32(const void* p) {
    uint32_t a;
    asm("{ .reg .u64 t; cvta.to.shared.u64 t, %1; cvt.u32.u64 %0, t; }"
        : "=r"(a) : "l"(p));
    return a;
}

__device__ __forceinline__ void mma_f16(float* d, const uint32_t* a,
                                        const uint32_t* b) {
    asm volatile(
        "mma.sync.aligned.m16n8k16.row.col.f32.f16.f16.f32 "
        "{%0,%1,%2,%3}, {%4,%5,%6,%7}, {%8,%9}, {%0,%1,%2,%3};"
        : "+f"(d[0]), "+f"(d[1]), "+f"(d[2]), "+f"(d[3])
        : "r"(a[0]), "r"(a[1]), "r"(a[2]), "r"(a[3]),
          "r"(b[0]), "r"(b[1]));
}

#define LDSM4(r0, r1, r2, r3, addr)                                           \
    asm volatile("ldmatrix.sync.aligned.m8n8.x4.shared.b16 {%0,%1,%2,%3}, [%4];" \
                 : "=r"(r0), "=r"(r1), "=r"(r2), "=r"(r3) : "r"(addr))

#define CP_ASYNC16(dst, src) \
    asm volatile("cp.async.cg.shared.global [%0], [%1], 16;" :: "r"(dst), "l"(src))
#define CP_COMMIT() asm volatile("cp.async.commit_group;" ::: "memory")
#define CP_WAIT1()  asm volatile("cp.async.wait_group 1;" ::: "memory")

__device__ __forceinline__ void store_out(float2 v, float* p) {
    *(float2*)p = v;
}
__device__ __forceinline__ void store_out(float2 v, __half* p) {
    *(__half2*)p = __floats2half2_rn(v.x, v.y);
}

// ---------------------------------------------------------------------------
// fp32 -> fp16 conversion
// ---------------------------------------------------------------------------
__global__ __launch_bounds__(256)
void cvt_f16(const float4* __restrict__ in, uint2* __restrict__ out, int n4) {
    int i = blockIdx.x * blockDim.x + threadIdx.x;
    if (i < n4) {
        float4 v = in[i];
        __half2 h0 = __floats2half2_rn(v.x, v.y);
        __half2 h1 = __floats2half2_rn(v.z, v.w);
        uint2 o;
        o.x = *(uint32_t*)&h0;
        o.y = *(uint32_t*)&h1;
        out[i] = o;
    }
}

// ---------------------------------------------------------------------------
// fp16 mma.sync GEMM (NT): C[m,n] = sum_k A[m,k]*B[n,k] + bias[n]
// 128x128 CTA tile, BK=64, 8 warps (4x2), 32x64 warp tile, 256 threads,
// 3-stage cp.async, XOR swizzle, ldmatrix. Output templated.
// ---------------------------------------------------------------------------
#define TILE_BYTES 16384
#define SMEM_F16   (3 * 2 * TILE_BYTES)

__device__ __forceinline__ void stage_ab(uint32_t base,
                                         const __half* __restrict__ A,
                                         const __half* __restrict__ B,
                                         int bm, int bn, int k0, int tid) {
#pragma unroll
    for (int i = 0; i < 4; ++i) {
        int f = i * 256 + tid;
        int row = f >> 3, c4 = f & 7;
        uint32_t dst = base + row * 128 + ((c4 ^ (row & 7)) << 4);
        const __half* src = A + (size_t)(bm + row) * 1024 + k0 + c4 * 8;
        CP_ASYNC16(dst, src);
    }
#pragma unroll
    for (int i = 0; i < 4; ++i) {
        int f = i * 256 + tid;
        int row = f >> 3, c4 = f & 7;
        uint32_t dst = base + TILE_BYTES + row * 128 + ((c4 ^ (row & 7)) << 4);
        const __half* src = B + (size_t)(bn + row) * 1024 + k0 + c4 * 8;
        CP_ASYNC16(dst, src);
    }
}

template <typename OT>
__global__ __launch_bounds__(256, 2)
void mma_gemm(const __half* __restrict__ A, const __half* __restrict__ B,
              const float* __restrict__ bias, OT* __restrict__ Cout) {
    extern __shared__ char dyn_smem[];
    const uint32_t sb = smem_u32(dyn_smem);

    const int tid  = threadIdx.x;
    const int wid  = tid >> 5;
    const int lane = tid & 31;
    const int g    = lane >> 2;
    const int tig  = lane & 3;
    const int wm   = wid >> 1;
    const int wn   = wid & 1;
    const int bm = blockIdx.y * 128;
    const int bn = blockIdx.x * 128;

    float d[2][8][4];
#pragma unroll
    for (int i = 0; i < 2; ++i)
#pragma unroll
        for (int j = 0; j < 8; ++j)
#pragma unroll
            for (int r = 0; r < 4; ++r) d[i][j][r] = 0.f;

    const int aHi = (lane >> 4) & 1;
    uint32_t aRowOff[2], aSw[2];
#pragma unroll
    for (int i = 0; i < 2; ++i) {
        int rowA = wm * 32 + i * 16 + (lane & 15);
        aRowOff[i] = (uint32_t)(rowA * 128);
        aSw[i] = (uint32_t)(rowA & 7);
    }
    const int bHi = (lane >> 3) & 1;
    uint32_t bRowOff[4], bSw[4];
#pragma unroll
    for (int j2 = 0; j2 < 4; ++j2) {
        int rowB = wn * 64 + j2 * 16 + ((lane & 16) >> 1) + (lane & 7);
        bRowOff[j2] = (uint32_t)(rowB * 128);
        bSw[j2] = (uint32_t)(rowB & 7);
    }

    stage_ab(sb + 0 * 32768, A, B, bm, bn, 0, tid);
    CP_COMMIT();
    stage_ab(sb + 1 * 32768, A, B, bm, bn, 64, tid);
    CP_COMMIT();

#pragma unroll 1
    for (int s = 0; s < 16; ++s) {
        CP_WAIT1();
        __syncthreads();

        if (s + 2 < 16)
            stage_ab(sb + ((s + 2) % 3) * 32768, A, B, bm, bn,
                     (s + 2) * 64, tid);
        CP_COMMIT();

        const uint32_t aBase = sb + (s % 3) * 32768;
        const uint32_t bBase = aBase + TILE_BYTES;

#pragma unroll
        for (int ks = 0; ks < 4; ++ks) {
            const uint32_t granA = (uint32_t)(2 * ks + aHi);
            const uint32_t granB = (uint32_t)(2 * ks + bHi);
            uint32_t af[2][4];
#pragma unroll
            for (int i = 0; i < 2; ++i) {
                uint32_t addr = aBase + aRowOff[i] + ((granA ^ aSw[i]) << 4);
                LDSM4(af[i][0], af[i][1], af[i][2], af[i][3], addr);
            }
            uint32_t bf[8][2];
#pragma unroll
            for (int j2 = 0; j2 < 4; ++j2) {
                uint32_t addr = bBase + bRowOff[j2] + ((granB ^ bSw[j2]) << 4);
                LDSM4(bf[2 * j2][0], bf[2 * j2][1],
                      bf[2 * j2 + 1][0], bf[2 * j2 + 1][1], addr);
            }
#pragma unroll
            for (int i = 0; i < 2; ++i)
#pragma unroll
                for (int j = 0; j < 8; ++j)
                    mma_f16(d[i][j], af[i], bf[j]);
        }
    }

#pragma unroll
    for (int i = 0; i < 2; ++i) {
        int row = bm + wm * 32 + i * 16 + g;
        OT* o0 = Cout + (size_t)row * 1024 + bn + wn * 64;
        OT* o1 = o0 + 8 * 1024;
#pragma unroll
        for (int j = 0; j < 8; ++j) {
            int col = j * 8 + tig * 2;
            float2 bb = *(const float2*)&bias[bn + wn * 64 + col];
            float2 v0, v1;
            v0.x = d[i][j][0] + bb.x;
            v0.y = d[i][j][1] + bb.y;
            v1.x = d[i][j][2] + bb.x;
            v1.y = d[i][j][3] + bb.y;
            store_out(v0, o0 + col);
            store_out(v1, o1 + col);
        }
    }
}

// ---------------------------------------------------------------------------
// Kernel A: depthwise conv(k=3,pad=1) + LayerNorm + exact GELU -> x_dw fp16.
// ---------------------------------------------------------------------------
__global__ __launch_bounds__(256)
void conv_ln_gelu(const float* __restrict__ x,
                  const float* __restrict__ dw_w, const float* __restrict__ dw_b,
                  const float* __restrict__ ln_g, const float* __restrict__ ln_b,
                  __half* __restrict__ xdw) {
    const int nl = blockIdx.x;
    const int l = nl & (LL - 1);
    const int tid = threadIdx.x;
    const int lane = tid & 31;
    const int wid = tid >> 5;
    const int c0 = tid * 4;

    const float* x0 = x + (size_t)nl * CC;

    float4 xm = *(const float4*)(x0 + c0);
    float4 xl = (l > 0)      ? *(const float4*)(x0 + c0 - CC) : make_float4(0,0,0,0);
    float4 xr = (l < LL - 1) ? *(const float4*)(x0 + c0 + CC) : make_float4(0,0,0,0);
    float4 db = *(const float4*)(dw_b + c0);
    float v[4];
    {
        const float* wp = dw_w + c0 * 3;
        v[0] = db.x + xl.x * wp[0]  + xm.x * wp[1]  + xr.x * wp[2];
        v[1] = db.y + xl.y * wp[3]  + xm.y * wp[4]  + xr.y * wp[5];
        v[2] = db.z + xl.z * wp[6]  + xm.z * wp[7]  + xr.z * wp[8];
        v[3] = db.w + xl.w * wp[9]  + xm.w * wp[10] + xr.w * wp[11];
    }

    float s  = v[0] + v[1] + v[2] + v[3];
    float s2 = v[0]*v[0] + v[1]*v[1] + v[2]*v[2] + v[3]*v[3];
#pragma unroll
    for (int o = 16; o; o >>= 1) {
        s  += __shfl_xor_sync(0xFFFFFFFFu, s,  o);
        s2 += __shfl_xor_sync(0xFFFFFFFFu, s2, o);
    }
    __shared__ float rs[8], rs2[8];
    __shared__ float stats[2];
    if (lane == 0) { rs[wid] = s; rs2[wid] = s2; }
    __syncthreads();
    if (tid == 0) {
        float S = 0.f, S2 = 0.f;
#pragma unroll
        for (int w = 0; w < 8; ++w) { S += rs[w]; S2 += rs2[w]; }
        float mu = S * (1.f / CC);
        float var = S2 * (1.f / CC) - mu * mu;
        stats[0] = mu;
        stats[1] = rsqrtf(var + 1e-5f);
    }
    __syncthreads();
    const float mu = stats[0], rstd = stats[1];

    float4 lg = *(const float4*)(ln_g + c0);
    float4 lb = *(const float4*)(ln_b + c0);
    float g0, g1, g2, g3, h;
    h = (v[0] - mu) * rstd * lg.x + lb.x;
    g0 = 0.5f * h * (1.f + erff(h * 0.70710678118654752f));
    h = (v[1] - mu) * rstd * lg.y + lb.y;
    g1 = 0.5f * h * (1.f + erff(h * 0.70710678118654752f));
    h = (v[2] - mu) * rstd * lg.z + lb.z;
    g2 = 0.5f * h * (1.f + erff(h * 0.70710678118654752f));
    h = (v[3] - mu) * rstd * lg.w + lb.w;
    g3 = 0.5f * h * (1.f + erff(h * 0.70710678118654752f));

    __half2 h0 = __floats2half2_rn(g0, g1);
    __half2 h1 = __floats2half2_rn(g2, g3);
    uint2 ov;
    ov.x = *(uint32_t*)&h0;
    ov.y = *(uint32_t*)&h1;
    *(uint2*)(xdw + (size_t)nl * CC + c0) = ov;
}

// ---------------------------------------------------------------------------
// Kernel B: offset/mask heads (fp16 weights) + softmax + positions.
// Warp per position, 8 per block; pos0 selects the chunk.
// ---------------------------------------------------------------------------
__global__ __launch_bounds__(256)
void heads_pos(const __half* __restrict__ xdw,
               const __half* __restrict__ Woh, const float* __restrict__ bo,
               const __half* __restrict__ Wmh, const float* __restrict__ bmv,
               float* __restrict__ recw, int* __restrict__ reci, int pos0) {
    const int wid  = threadIdx.x >> 5;
    const int lane = threadIdx.x & 31;
    const int pos  = pos0 + blockIdx.x * 8 + wid;
    const int l    = pos & (LL - 1);

    const __half2* xr  = (const __half2*)(xdw + (size_t)pos * CC);
    const __half2* wo2 = (const __half2*)Woh;
    const __half2* wm2 = (const __half2*)Wmh;

    float p[14];
#pragma unroll
    for (int j = 0; j < 14; ++j) p[j] = 0.f;

#pragma unroll
    for (int i = 0; i < 16; ++i) {
        int c2 = lane + 32 * i;
        float2 f = __half22float2(xr[c2]);
#pragma unroll
        for (int j = 0; j < 7; ++j) {
            float2 w1 = __half22float2(wo2[j * 512 + c2]);
            float2 w2 = __half22float2(wm2[j * 512 + c2]);
            p[j]     = fmaf(f.x, w1.x, fmaf(f.y, w1.y, p[j]));
            p[7 + j] = fmaf(f.x, w2.x, fmaf(f.y, w2.y, p[7 + j]));
        }
    }
#pragma unroll
    for (int o = 16; o; o >>= 1)
#pragma unroll
        for (int j = 0; j < 14; ++j)
            p[j] += __shfl_xor_sync(0xFFFFFFFFu, p[j], o);

    if (lane == 0) {
        float ho[KK], hm[KK];
#pragma unroll
        for (int j = 0; j < KK; ++j) {
            ho[j] = (p[j] + bo[j]) * 2.0f;     // OFFSET_SCALE
            hm[j] = p[7 + j] + bmv[j];
        }
        float mx = hm[0];
#pragma unroll
        for (int j = 1; j < KK; ++j) mx = fmaxf(mx, hm[j]);
        float e[KK], se = 0.f;
#pragma unroll
        for (int j = 0; j < KK; ++j) { e[j] = expf(hm[j] - mx); se += e[j]; }
        float inv = 1.f / se;

        float* rw = recw + (size_t)pos * 16;
        int*   ri = reci + (size_t)pos * 16;
#pragma unroll
        for (int k = 0; k < KK; ++k) {
            float mask = e[k] * inv;
            float ap  = (float)l + (float)(k - 3) + ho[k];
            float apc = fminf(fmaxf(ap, 0.f), (float)(LL - 1));
            int pf = (int)apc;
            if (pf > LL - 1) pf = LL - 1;
            int pc = pf + 1; if (pc > LL - 1) pc = LL - 1;
            float wc = apc - (float)pf;
            float wf = 1.f - wc;
            float valid = (ap < 0.f || ap > (float)(LL - 1)) ? 0.f : 1.f;
            rw[k]     = wf * valid * mask;
            rw[8 + k] = wc * valid * mask;
            ri[k]     = pf;
            ri[8 + k] = pc;
        }
    }
}

// ---------------------------------------------------------------------------
// Kernel C: gather-blend from fp16 x_proj -> sampled fp16; nl0 selects chunk.
// ---------------------------------------------------------------------------
__global__ __launch_bounds__(128)
void gather_blend(const __half* __restrict__ xph,
                  const float* __restrict__ recw, const int* __restrict__ reci,
                  __half* __restrict__ samp, int nl0) {
    const int nl = nl0 + blockIdx.x;
    const int n  = nl >> 11;
    const int c0 = threadIdx.x * 8;

    const float* rw = recw + (size_t)nl * 16;
    const int*   ri = reci + (size_t)nl * 16;

    float wf[KK], wc[KK];
    int   pf[KK], pc[KK];
#pragma unroll
    for (int k = 0; k < KK; ++k) {
        wf[k] = __ldg(rw + k);
        wc[k] = __ldg(rw + 8 + k);
        pf[k] = __ldg(ri + k);
        pc[k] = __ldg(ri + 8 + k);
    }

    const __half* xpn = xph + (size_t)n * LL * CC + c0;

    float acc[8];
#pragma unroll
    for (int m = 0; m < 8; ++m) acc[m] = 0.f;

#pragma unroll
    for (int k = 0; k < KK; ++k) {
        uint4 rf = *(const uint4*)(xpn + (size_t)pf[k] * CC);
        uint4 rc = *(const uint4*)(xpn + (size_t)pc[k] * CC);
        float w0 = wf[k], w1 = wc[k];
        const __half2* hf = (const __half2*)&rf;
        const __half2* hc = (const __half2*)&rc;
#pragma unroll
        for (int m = 0; m < 4; ++m) {
            float2 ff = __half22float2(hf[m]);
            float2 fc = __half22float2(hc[m]);
            acc[2*m + 0] = fmaf(ff.x, w0, fmaf(fc.x, w1, acc[2*m + 0]));
            acc[2*m + 1] = fmaf(ff.y, w0, fmaf(fc.y, w1, acc[2*m + 1]));
        }
    }

    uint4 ov;
    __half2 o0 = __floats2half2_rn(acc[0], acc[1]);
    __half2 o1 = __floats2half2_rn(acc[2], acc[3]);
    __half2 o2 = __floats2half2_rn(acc[4], acc[5]);
    __half2 o3 = __floats2half2_rn(acc[6], acc[7]);
    ov.x = *(uint32_t*)&o0; ov.y = *(uint32_t*)&o1;
    ov.z = *(uint32_t*)&o2; ov.w = *(uint32_t*)&o3;
    *(uint4*)(samp + (size_t)nl * CC + c0) = ov;
}

// ---------------------------------------------------------------------------
// Launch — 2-chunk pipeline (chunks = 2 batches each, gathers chunk-local):
//
//   main: cvt_x, cvt_wi, G1a -[g1a]-> G1b -[g1b]
//   side: cvt_wo, cvt_wo7, cvt_wm7, A, B_a -[b1]-> B_b -[b2]
//   s2:   wait(g1a,b1) C_a -> G2a ; wait(g1b,b2) C_b -> G2b -[done]
//   main: wait(done)
// ---------------------------------------------------------------------------
extern "C" void kernel_launch(void* const* d_in, const int* in_sizes, int n_in,
                              void* d_out, int out_size) {
    const float* x    = (const float*)d_in[0];
    const float* Wi   = (const float*)d_in[1];
    const float* bi   = (const float*)d_in[2];
    const float* dw_w = (const float*)d_in[3];
    const float* dw_b = (const float*)d_in[4];
    const float* ln_g = (const float*)d_in[5];
    const float* ln_b = (const float*)d_in[6];
    const float* Wo   = (const float*)d_in[7];
    const float* bo   = (const float*)d_in[8];
    const float* Wm   = (const float*)d_in[9];
    const float* bmv  = (const float*)d_in[10];
    const float* Wout = (const float*)d_in[11];
    const float* bout = (const float*)d_in[12];
    float* out = (float*)d_out;

    __half *xh, *wih, *woh, *woh7, *wmh7, *xph, *xdw, *samph;
    float *recw;
    int *reci;
    cudaGetSymbolAddress((void**)&xh,    g_xh);
    cudaGetSymbolAddress((void**)&wih,   g_wih);
    cudaGetSymbolAddress((void**)&woh,   g_woh);
    cudaGetSymbolAddress((void**)&woh7,  g_woh7);
    cudaGetSymbolAddress((void**)&wmh7,  g_wmh7);
    cudaGetSymbolAddress((void**)&xph,   g_xph);
    cudaGetSymbolAddress((void**)&xdw,   g_xdw);
    cudaGetSymbolAddress((void**)&samph, g_samph);
    cudaGetSymbolAddress((void**)&recw,  g_recw);
    cudaGetSymbolAddress((void**)&reci,  g_reci);

    cudaFuncSetAttribute(mma_gemm<__half>,
                         cudaFuncAttributeMaxDynamicSharedMemorySize, SMEM_F16);
    cudaFuncSetAttribute(mma_gemm<float>,
                         cudaFuncAttributeMaxDynamicSharedMemorySize, SMEM_F16);

    // One-time host-side stream/event creation (no device memory involved).
    static cudaStream_t s_side = nullptr, s2 = nullptr;
    static cudaEvent_t ev_fork = nullptr, ev_b1 = nullptr, ev_b2 = nullptr,
                       ev_g1a = nullptr, ev_g1b = nullptr, ev_done = nullptr;
    if (s_side == nullptr) {
        cudaStreamCreateWithFlags(&s_side, cudaStreamNonBlocking);
        cudaStreamCreateWithFlags(&s2, cudaStreamNonBlocking);
        cudaEventCreateWithFlags(&ev_fork, cudaEventDisableTiming);
        cudaEventCreateWithFlags(&ev_b1,   cudaEventDisableTiming);
        cudaEventCreateWithFlags(&ev_b2,   cudaEventDisableTiming);
        cudaEventCreateWithFlags(&ev_g1a,  cudaEventDisableTiming);
        cudaEventCreateWithFlags(&ev_g1b,  cudaEventDisableTiming);
        cudaEventCreateWithFlags(&ev_done, cudaEventDisableTiming);
    }

    dim3 half_grid(CC / 128, HM / 128);   // (8, 32)

    // Fork side streams off the main (legacy) stream.
    cudaEventRecord(ev_fork, 0);
    cudaStreamWaitEvent(s_side, ev_fork, 0);
    cudaStreamWaitEvent(s2, ev_fork, 0);

    // --- side: weight cvts, A (full), B per chunk ---
    cvt_f16<<<(CC * CC / 4) / 256, 256, 0, s_side>>>(
        (const float4*)Wout, (uint2*)woh, CC * CC / 4);
    cvt_f16<<<(KK * CC / 4 + 255) / 256, 256, 0, s_side>>>(
        (const float4*)Wo, (uint2*)woh7, KK * CC / 4);
    cvt_f16<<<(KK * CC / 4 + 255) / 256, 256, 0, s_side>>>(
        (const float4*)Wm, (uint2*)wmh7, KK * CC / 4);
    conv_ln_gelu<<<MM, 256, 0, s_side>>>(x, dw_w, dw_b, ln_g, ln_b, xdw);
    heads_pos<<<HM / 8, 256, 0, s_side>>>(xdw, woh7, bo, wmh7, bmv,
                                          recw, reci, 0);
    cudaEventRecord(ev_b1, s_side);
    heads_pos<<<HM / 8, 256, 0, s_side>>>(xdw, woh7, bo, wmh7, bmv,
                                          recw, reci, HM);
    cudaEventRecord(ev_b2, s_side);

    // --- main: cvt x, cvt Wi, GEMM1 chunk a, chunk b ---
    cvt_f16<<<(MM * CC / 4) / 256, 256>>>((const float4*)x, (uint2*)xh,
                                          MM * CC / 4);
    cvt_f16<<<(CC * CC / 4) / 256, 256>>>((const float4*)Wi, (uint2*)wih,
                                          CC * CC / 4);
    mma_gemm<__half><<<half_grid, 256, SMEM_F16>>>(xh, wih, bi, xph);
    cudaEventRecord(ev_g1a, 0);
    mma_gemm<__half><<<half_grid, 256, SMEM_F16>>>(xh + (size_t)HM * CC, wih,
                                                   bi, xph + (size_t)HM * CC);
    cudaEventRecord(ev_g1b, 0);

    // --- s2: chunk-a epilogue pipeline, then chunk-b ---
    cudaStreamWaitEvent(s2, ev_g1a, 0);
    cudaStreamWaitEvent(s2, ev_b1, 0);
    gather_blend<<<HM, 128, 0, s2>>>(xph, recw, reci, samph, 0);
    mma_gemm<float><<<half_grid, 256, SMEM_F16, s2>>>(samph, woh, bout, out);

    cudaStreamWaitEvent(s2, ev_g1b, 0);
    cudaStreamWaitEvent(s2, ev_b2, 0);
    gather_blend<<<HM, 128, 0, s2>>>(xph, recw, reci, samph, HM);
    mma_gemm<float><<<half_grid, 256, SMEM_F16, s2>>>(samph + (size_t)HM * CC,
                                                      woh, bout,
                                                      out + (size_t)HM * CC);
    cudaEventRecord(ev_done, s2);

    // join everything back to the main stream
    cudaStreamWaitEvent(0, ev_done, 0);
}